// round 5
// baseline (speedup 1.0000x reference)
#include <cuda_runtime.h>

// LSTMAnomalyDetector: B=4096, T=512, I=3, H=64 (PyTorch gate order i,f,g,o)
// Persistent CTA: 128 CTAs x 512 threads, 32 batch rows per CTA, all 512 steps on-chip.
//
// Round-3: thread owns (1 unit x 4 rows). 16 warps/SM (4 per SMSP) to hide LDS
// latency; 8 fma2 accumulators; per k: 3 LDS.128 + 8 fma.rn.f32x2.
// W_hh pre-duplicated in smem as (w,w) pairs -> no packing MOVs in the hot loop.

#define B_  4096
#define T_  512
#define H_  64
#define RT  32       // rows per CTA
#define NT  512      // threads per CTA
#define HP  36       // hsh row pitch in floats

typedef unsigned long long ull;

__device__ __forceinline__ float tanhfast(float x) {
    float y; asm("tanh.approx.f32 %0, %1;" : "=f"(y) : "f"(x)); return y;
}
__device__ __forceinline__ float sigf(float x) {
    return fmaf(0.5f, tanhfast(0.5f * x), 0.5f);
}
__device__ __forceinline__ ull pack2(float a, float b) {
    ull r; asm("mov.b64 %0, {%1, %2};" : "=l"(r) : "f"(a), "f"(b)); return r;
}
__device__ __forceinline__ void unpack2(ull v, float& lo, float& hi) {
    asm("mov.b64 {%0, %1}, %2;" : "=f"(lo), "=f"(hi) : "l"(v));
}
__device__ __forceinline__ ull fma2(ull a, ull b, ull c) {
    ull d; asm("fma.rn.f32x2 %0, %1, %2, %3;" : "=l"(d) : "l"(a), "l"(b), "l"(c)); return d;
}

struct Smem {
    ulonglong2 W01[H_][H_];   // 64KB  [k][u]: ((wi,wi),(wf,wf))
    ulonglong2 W23[H_][H_];   // 64KB  [k][u]: ((wg,wg),(wo,wo))
    float hsh[2][H_][HP];     // [buf][unit k][row], pitch 36
    float xsh[2][3][RT];      // x double buffer, transposed [i][row]
    float wdec[3][H_];
};
#define SMEM_BYTES ((int)sizeof(Smem))

extern __shared__ char smem_raw[];

__global__ void __launch_bounds__(NT, 1)
lstm_persistent_kernel(const float* __restrict__ x,      // [B, T, 3]
                       const float* __restrict__ Wih,    // [256, 3]
                       const float* __restrict__ Whh,    // [256, 64]
                       const float* __restrict__ bih,    // [256]
                       const float* __restrict__ bhh,    // [256]
                       const float* __restrict__ Wdec,   // [3, 64]
                       const float* __restrict__ bdec,   // [3]
                       float* __restrict__ out)          // [B, T, 3]
{
    Smem* S = (Smem*)smem_raw;
    const int tid  = threadIdx.x;
    const int row0 = blockIdx.x * RT;

    const int u  = tid >> 3;        // unit 0..63 owned by this thread
    const int rg = tid & 7;         // row group: rows 4rg .. 4rg+3

    // ---- setup -----------------------------------------------------------
    for (int idx = tid; idx < H_ * H_; idx += NT) {
        const int k = idx >> 6, uu = idx & 63;
        const float wi = Whh[(0 * H_ + uu) * H_ + k];
        const float wf = Whh[(1 * H_ + uu) * H_ + k];
        const float wg = Whh[(2 * H_ + uu) * H_ + k];
        const float wo = Whh[(3 * H_ + uu) * H_ + k];
        *(float4*)&S->W01[k][uu] = make_float4(wi, wi, wf, wf);
        *(float4*)&S->W23[k][uu] = make_float4(wg, wg, wo, wo);
    }
    for (int i = tid; i < 2 * H_ * HP; i += NT) ((float*)S->hsh)[i] = 0.0f;
    if (tid < 3 * H_) ((float*)S->wdec)[tid] = Wdec[tid];

    // per-thread W_ih (duplicated) and bias in registers
    ull wih2[4][3], biasp[4];
#pragma unroll
    for (int gt = 0; gt < 4; gt++) {
        const int g = gt * H_ + u;
        const float b = bih[g] + bhh[g];
        biasp[gt] = pack2(b, b);
#pragma unroll
        for (int i = 0; i < 3; i++) {
            const float wv = Wih[g * 3 + i];
            wih2[gt][i] = pack2(wv, wv);
        }
    }

    // decode / x-staging roles (threads 0..95)
    const int dro = tid >> 5;       // output/x component (0..2) for tid<96
    const int drr = tid & 31;       // row
    float bd = 0.0f;
    if (tid < 96) {
        bd = bdec[dro];
        S->xsh[0][dro][drr] = x[((size_t)(row0 + drr) * T_ + 0) * 3 + dro];
    }

    float c[4];
#pragma unroll
    for (int p = 0; p < 4; p++) c[p] = 0.0f;

    __syncthreads();

    // ---- timestep loop -----------------------------------------------------
    for (int t = 0; t < T_; t++) {
        const int A = t & 1, Bb = A ^ 1;

        // prefetch x(t+1): global latency hidden under the matvec
        float xp = 0.0f;
        if (tid < 96 && (t + 1) < T_)
            xp = x[((size_t)(row0 + drr) * T_ + (t + 1)) * 3 + dro];

        // decode previous step's h -> out[., t-1, .]
        if (t > 0 && tid < 96) {
            const float* hp_ = &S->hsh[A][0][drr];
            const float* wd  = &S->wdec[dro][0];
            float s0 = 0.f, s1 = 0.f, s2 = 0.f, s3 = 0.f;
#pragma unroll 4
            for (int k = 0; k < H_; k += 4) {
                s0 = fmaf(hp_[(k + 0) * HP], wd[k + 0], s0);
                s1 = fmaf(hp_[(k + 1) * HP], wd[k + 1], s1);
                s2 = fmaf(hp_[(k + 2) * HP], wd[k + 2], s2);
                s3 = fmaf(hp_[(k + 3) * HP], wd[k + 3], s3);
            }
            out[((size_t)(row0 + drr) * T_ + (t - 1)) * 3 + dro] = (s0 + s1) + (s2 + s3) + bd;
        }

        // accumulators: a[gate][pair]; pair 0 = rows (4rg,4rg+1), pair 1 = rows (4rg+2,4rg+3)
        ull a0[2], a1[2], a2[2], a3[2];
        a0[0] = biasp[0]; a0[1] = biasp[0];
        a1[0] = biasp[1]; a1[1] = biasp[1];
        a2[0] = biasp[2]; a2[1] = biasp[2];
        a3[0] = biasp[3]; a3[1] = biasp[3];

        // input contribution: + W_ih * x(t)
#pragma unroll
        for (int i = 0; i < 3; i++) {
            const ulonglong2 xv = *(const ulonglong2*)&S->xsh[A][i][4 * rg];
            a0[0] = fma2(xv.x, wih2[0][i], a0[0]);  a0[1] = fma2(xv.y, wih2[0][i], a0[1]);
            a1[0] = fma2(xv.x, wih2[1][i], a1[0]);  a1[1] = fma2(xv.y, wih2[1][i], a1[1]);
            a2[0] = fma2(xv.x, wih2[2][i], a2[0]);  a2[1] = fma2(xv.y, wih2[2][i], a2[1]);
            a3[0] = fma2(xv.x, wih2[3][i], a3[0]);  a3[1] = fma2(xv.y, wih2[3][i], a3[1]);
        }

        // recurrent matvec: per k, 3x LDS.128 + 8x fma.rn.f32x2
        {
            const float* hrow = &S->hsh[A][0][4 * rg];
            const ulonglong2* w01p = &S->W01[0][u];
            const ulonglong2* w23p = &S->W23[0][u];
#pragma unroll 4
            for (int k = 0; k < H_; k++) {
                const ulonglong2 hv  = *(const ulonglong2*)(hrow);   // 4 rows
                const ulonglong2 w01 = w01p[k * H_];
                const ulonglong2 w23 = w23p[k * H_];
                a0[0] = fma2(hv.x, w01.x, a0[0]);
                a0[1] = fma2(hv.y, w01.x, a0[1]);
                a1[0] = fma2(hv.x, w01.y, a1[0]);
                a1[1] = fma2(hv.y, w01.y, a1[1]);
                a2[0] = fma2(hv.x, w23.x, a2[0]);
                a2[1] = fma2(hv.y, w23.x, a2[1]);
                a3[0] = fma2(hv.x, w23.y, a3[0]);
                a3[1] = fma2(hv.y, w23.y, a3[1]);
                hrow += HP;
            }
        }

        // nonlinearities + state update on 4 (row, unit u) cells
        float hout[4];
#pragma unroll
        for (int pr = 0; pr < 2; pr++) {
            float gi0, gi1, gf0, gf1, gg0, gg1, go0, go1;
            unpack2(a0[pr], gi0, gi1);
            unpack2(a1[pr], gf0, gf1);
            unpack2(a2[pr], gg0, gg1);
            unpack2(a3[pr], go0, go1);
            {
                const float ig = sigf(gi0), fg = sigf(gf0), gg = tanhfast(gg0), og = sigf(go0);
                const float cn = fmaf(fg, c[2 * pr], ig * gg);
                c[2 * pr] = cn;
                hout[2 * pr] = og * tanhfast(cn);
            }
            {
                const float ig = sigf(gi1), fg = sigf(gf1), gg = tanhfast(gg1), og = sigf(go1);
                const float cn = fmaf(fg, c[2 * pr + 1], ig * gg);
                c[2 * pr + 1] = cn;
                hout[2 * pr + 1] = og * tanhfast(cn);
            }
        }
        *(float4*)&S->hsh[Bb][u][4 * rg] = make_float4(hout[0], hout[1], hout[2], hout[3]);

        // stage x(t+1)
        if (tid < 96) S->xsh[Bb][dro][drr] = xp;

        __syncthreads();
    }

    // epilogue: decode h(T-1) (buffer 0 after the last flip)
    if (tid < 96) {
        const float* hp_ = &S->hsh[0][0][drr];
        const float* wd  = &S->wdec[dro][0];
        float s0 = 0.f, s1 = 0.f, s2 = 0.f, s3 = 0.f;
#pragma unroll 4
        for (int k = 0; k < H_; k += 4) {
            s0 = fmaf(hp_[(k + 0) * HP], wd[k + 0], s0);
            s1 = fmaf(hp_[(k + 1) * HP], wd[k + 1], s1);
            s2 = fmaf(hp_[(k + 2) * HP], wd[k + 2], s2);
            s3 = fmaf(hp_[(k + 3) * HP], wd[k + 3], s3);
        }
        out[((size_t)(row0 + drr) * T_ + (T_ - 1)) * 3 + dro] = (s0 + s1) + (s2 + s3) + bd;
    }
}

extern "C" void kernel_launch(void* const* d_in, const int* in_sizes, int n_in,
                              void* d_out, int out_size) {
    const float* x    = (const float*)d_in[0];
    const float* Wih  = (const float*)d_in[1];
    const float* Whh  = (const float*)d_in[2];
    const float* bih  = (const float*)d_in[3];
    const float* bhh  = (const float*)d_in[4];
    const float* Wdec = (const float*)d_in[5];
    const float* bdec = (const float*)d_in[6];
    float* out = (float*)d_out;

    cudaFuncSetAttribute(lstm_persistent_kernel,
                         cudaFuncAttributeMaxDynamicSharedMemorySize, SMEM_BYTES);
    lstm_persistent_kernel<<<B_ / RT, NT, SMEM_BYTES>>>(x, Wih, Whh, bih, bhh, Wdec, bdec, out);
}

// round 6
// speedup vs baseline: 1.0004x; 1.0004x over previous
#include <cuda_runtime.h>

// LSTMAnomalyDetector: B=4096, T=512, I=3, H=64 (PyTorch gate order i,f,g,o)
// Persistent CTA: 128 CTAs x 512 threads, 32 batch rows per CTA, all 512 steps on-chip.
//
// Round-3: thread owns (1 unit x 4 rows). 16 warps/SM (4 per SMSP) to hide LDS
// latency; 8 fma2 accumulators; per k: 3 LDS.128 + 8 fma.rn.f32x2.
// W_hh pre-duplicated in smem as (w,w) pairs -> no packing MOVs in the hot loop.

#define B_  4096
#define T_  512
#define H_  64
#define RT  32       // rows per CTA
#define NT  512      // threads per CTA
#define HP  36       // hsh row pitch in floats

typedef unsigned long long ull;

__device__ __forceinline__ float tanhfast(float x) {
    float y; asm("tanh.approx.f32 %0, %1;" : "=f"(y) : "f"(x)); return y;
}
__device__ __forceinline__ float sigf(float x) {
    return fmaf(0.5f, tanhfast(0.5f * x), 0.5f);
}
__device__ __forceinline__ ull pack2(float a, float b) {
    ull r; asm("mov.b64 %0, {%1, %2};" : "=l"(r) : "f"(a), "f"(b)); return r;
}
__device__ __forceinline__ void unpack2(ull v, float& lo, float& hi) {
    asm("mov.b64 {%0, %1}, %2;" : "=f"(lo), "=f"(hi) : "l"(v));
}
__device__ __forceinline__ ull fma2(ull a, ull b, ull c) {
    ull d; asm("fma.rn.f32x2 %0, %1, %2, %3;" : "=l"(d) : "l"(a), "l"(b), "l"(c)); return d;
}

struct Smem {
    ulonglong2 W01[H_][H_];   // 64KB  [k][u]: ((wi,wi),(wf,wf))
    ulonglong2 W23[H_][H_];   // 64KB  [k][u]: ((wg,wg),(wo,wo))
    float hsh[2][H_][HP];     // [buf][unit k][row], pitch 36
    float xsh[2][3][RT];      // x double buffer, transposed [i][row]
    float wdec[3][H_];
};
#define SMEM_BYTES ((int)sizeof(Smem))

extern __shared__ char smem_raw[];

__global__ void __launch_bounds__(NT, 1)
lstm_persistent_kernel(const float* __restrict__ x,      // [B, T, 3]
                       const float* __restrict__ Wih,    // [256, 3]
                       const float* __restrict__ Whh,    // [256, 64]
                       const float* __restrict__ bih,    // [256]
                       const float* __restrict__ bhh,    // [256]
                       const float* __restrict__ Wdec,   // [3, 64]
                       const float* __restrict__ bdec,   // [3]
                       float* __restrict__ out)          // [B, T, 3]
{
    Smem* S = (Smem*)smem_raw;
    const int tid  = threadIdx.x;
    const int row0 = blockIdx.x * RT;

    const int u  = tid >> 3;        // unit 0..63 owned by this thread
    const int rg = tid & 7;         // row group: rows 4rg .. 4rg+3

    // ---- setup -----------------------------------------------------------
    for (int idx = tid; idx < H_ * H_; idx += NT) {
        const int k = idx >> 6, uu = idx & 63;
        const float wi = Whh[(0 * H_ + uu) * H_ + k];
        const float wf = Whh[(1 * H_ + uu) * H_ + k];
        const float wg = Whh[(2 * H_ + uu) * H_ + k];
        const float wo = Whh[(3 * H_ + uu) * H_ + k];
        *(float4*)&S->W01[k][uu] = make_float4(wi, wi, wf, wf);
        *(float4*)&S->W23[k][uu] = make_float4(wg, wg, wo, wo);
    }
    for (int i = tid; i < 2 * H_ * HP; i += NT) ((float*)S->hsh)[i] = 0.0f;
    if (tid < 3 * H_) ((float*)S->wdec)[tid] = Wdec[tid];

    // per-thread W_ih (duplicated) and bias in registers
    ull wih2[4][3], biasp[4];
#pragma unroll
    for (int gt = 0; gt < 4; gt++) {
        const int g = gt * H_ + u;
        const float b = bih[g] + bhh[g];
        biasp[gt] = pack2(b, b);
#pragma unroll
        for (int i = 0; i < 3; i++) {
            const float wv = Wih[g * 3 + i];
            wih2[gt][i] = pack2(wv, wv);
        }
    }

    // decode / x-staging roles (threads 0..95)
    const int dro = tid >> 5;       // output/x component (0..2) for tid<96
    const int drr = tid & 31;       // row
    float bd = 0.0f;
    if (tid < 96) {
        bd = bdec[dro];
        S->xsh[0][dro][drr] = x[((size_t)(row0 + drr) * T_ + 0) * 3 + dro];
    }

    float c[4];
#pragma unroll
    for (int p = 0; p < 4; p++) c[p] = 0.0f;

    __syncthreads();

    // ---- timestep loop -----------------------------------------------------
    for (int t = 0; t < T_; t++) {
        const int A = t & 1, Bb = A ^ 1;

        // prefetch x(t+1): global latency hidden under the matvec
        float xp = 0.0f;
        if (tid < 96 && (t + 1) < T_)
            xp = x[((size_t)(row0 + drr) * T_ + (t + 1)) * 3 + dro];

        // decode previous step's h -> out[., t-1, .]
        if (t > 0 && tid < 96) {
            const float* hp_ = &S->hsh[A][0][drr];
            const float* wd  = &S->wdec[dro][0];
            float s0 = 0.f, s1 = 0.f, s2 = 0.f, s3 = 0.f;
#pragma unroll 4
            for (int k = 0; k < H_; k += 4) {
                s0 = fmaf(hp_[(k + 0) * HP], wd[k + 0], s0);
                s1 = fmaf(hp_[(k + 1) * HP], wd[k + 1], s1);
                s2 = fmaf(hp_[(k + 2) * HP], wd[k + 2], s2);
                s3 = fmaf(hp_[(k + 3) * HP], wd[k + 3], s3);
            }
            out[((size_t)(row0 + drr) * T_ + (t - 1)) * 3 + dro] = (s0 + s1) + (s2 + s3) + bd;
        }

        // accumulators: a[gate][pair]; pair 0 = rows (4rg,4rg+1), pair 1 = rows (4rg+2,4rg+3)
        ull a0[2], a1[2], a2[2], a3[2];
        a0[0] = biasp[0]; a0[1] = biasp[0];
        a1[0] = biasp[1]; a1[1] = biasp[1];
        a2[0] = biasp[2]; a2[1] = biasp[2];
        a3[0] = biasp[3]; a3[1] = biasp[3];

        // input contribution: + W_ih * x(t)
#pragma unroll
        for (int i = 0; i < 3; i++) {
            const ulonglong2 xv = *(const ulonglong2*)&S->xsh[A][i][4 * rg];
            a0[0] = fma2(xv.x, wih2[0][i], a0[0]);  a0[1] = fma2(xv.y, wih2[0][i], a0[1]);
            a1[0] = fma2(xv.x, wih2[1][i], a1[0]);  a1[1] = fma2(xv.y, wih2[1][i], a1[1]);
            a2[0] = fma2(xv.x, wih2[2][i], a2[0]);  a2[1] = fma2(xv.y, wih2[2][i], a2[1]);
            a3[0] = fma2(xv.x, wih2[3][i], a3[0]);  a3[1] = fma2(xv.y, wih2[3][i], a3[1]);
        }

        // recurrent matvec: per k, 3x LDS.128 + 8x fma.rn.f32x2
        {
            const float* hrow = &S->hsh[A][0][4 * rg];
            const ulonglong2* w01p = &S->W01[0][u];
            const ulonglong2* w23p = &S->W23[0][u];
#pragma unroll 4
            for (int k = 0; k < H_; k++) {
                const ulonglong2 hv  = *(const ulonglong2*)(hrow);   // 4 rows
                const ulonglong2 w01 = w01p[k * H_];
                const ulonglong2 w23 = w23p[k * H_];
                a0[0] = fma2(hv.x, w01.x, a0[0]);
                a0[1] = fma2(hv.y, w01.x, a0[1]);
                a1[0] = fma2(hv.x, w01.y, a1[0]);
                a1[1] = fma2(hv.y, w01.y, a1[1]);
                a2[0] = fma2(hv.x, w23.x, a2[0]);
                a2[1] = fma2(hv.y, w23.x, a2[1]);
                a3[0] = fma2(hv.x, w23.y, a3[0]);
                a3[1] = fma2(hv.y, w23.y, a3[1]);
                hrow += HP;
            }
        }

        // nonlinearities + state update on 4 (row, unit u) cells
        float hout[4];
#pragma unroll
        for (int pr = 0; pr < 2; pr++) {
            float gi0, gi1, gf0, gf1, gg0, gg1, go0, go1;
            unpack2(a0[pr], gi0, gi1);
            unpack2(a1[pr], gf0, gf1);
            unpack2(a2[pr], gg0, gg1);
            unpack2(a3[pr], go0, go1);
            {
                const float ig = sigf(gi0), fg = sigf(gf0), gg = tanhfast(gg0), og = sigf(go0);
                const float cn = fmaf(fg, c[2 * pr], ig * gg);
                c[2 * pr] = cn;
                hout[2 * pr] = og * tanhfast(cn);
            }
            {
                const float ig = sigf(gi1), fg = sigf(gf1), gg = tanhfast(gg1), og = sigf(go1);
                const float cn = fmaf(fg, c[2 * pr + 1], ig * gg);
                c[2 * pr + 1] = cn;
                hout[2 * pr + 1] = og * tanhfast(cn);
            }
        }
        *(float4*)&S->hsh[Bb][u][4 * rg] = make_float4(hout[0], hout[1], hout[2], hout[3]);

        // stage x(t+1)
        if (tid < 96) S->xsh[Bb][dro][drr] = xp;

        __syncthreads();
    }

    // epilogue: decode h(T-1) (buffer 0 after the last flip)
    if (tid < 96) {
        const float* hp_ = &S->hsh[0][0][drr];
        const float* wd  = &S->wdec[dro][0];
        float s0 = 0.f, s1 = 0.f, s2 = 0.f, s3 = 0.f;
#pragma unroll 4
        for (int k = 0; k < H_; k += 4) {
            s0 = fmaf(hp_[(k + 0) * HP], wd[k + 0], s0);
            s1 = fmaf(hp_[(k + 1) * HP], wd[k + 1], s1);
            s2 = fmaf(hp_[(k + 2) * HP], wd[k + 2], s2);
            s3 = fmaf(hp_[(k + 3) * HP], wd[k + 3], s3);
        }
        out[((size_t)(row0 + drr) * T_ + (T_ - 1)) * 3 + dro] = (s0 + s1) + (s2 + s3) + bd;
    }
}

extern "C" void kernel_launch(void* const* d_in, const int* in_sizes, int n_in,
                              void* d_out, int out_size) {
    const float* x    = (const float*)d_in[0];
    const float* Wih  = (const float*)d_in[1];
    const float* Whh  = (const float*)d_in[2];
    const float* bih  = (const float*)d_in[3];
    const float* bhh  = (const float*)d_in[4];
    const float* Wdec = (const float*)d_in[5];
    const float* bdec = (const float*)d_in[6];
    float* out = (float*)d_out;

    cudaFuncSetAttribute(lstm_persistent_kernel,
                         cudaFuncAttributeMaxDynamicSharedMemorySize, SMEM_BYTES);
    lstm_persistent_kernel<<<B_ / RT, NT, SMEM_BYTES>>>(x, Wih, Whh, bih, bhh, Wdec, bdec, out);
}

// round 7
// speedup vs baseline: 1.0012x; 1.0008x over previous
#include <cuda_runtime.h>

// LSTMAnomalyDetector: B=4096, T=512, I=3, H=64 (PyTorch gate order i,f,g,o)
// Persistent CTA: 128 CTAs x 512 threads, 32 batch rows per CTA, all 512 steps on-chip.
//
// Round-3: thread owns (1 unit x 4 rows). 16 warps/SM (4 per SMSP) to hide LDS
// latency; 8 fma2 accumulators; per k: 3 LDS.128 + 8 fma.rn.f32x2.
// W_hh pre-duplicated in smem as (w,w) pairs -> no packing MOVs in the hot loop.

#define B_  4096
#define T_  512
#define H_  64
#define RT  32       // rows per CTA
#define NT  512      // threads per CTA
#define HP  36       // hsh row pitch in floats

typedef unsigned long long ull;

__device__ __forceinline__ float tanhfast(float x) {
    float y; asm("tanh.approx.f32 %0, %1;" : "=f"(y) : "f"(x)); return y;
}
__device__ __forceinline__ float sigf(float x) {
    return fmaf(0.5f, tanhfast(0.5f * x), 0.5f);
}
__device__ __forceinline__ ull pack2(float a, float b) {
    ull r; asm("mov.b64 %0, {%1, %2};" : "=l"(r) : "f"(a), "f"(b)); return r;
}
__device__ __forceinline__ void unpack2(ull v, float& lo, float& hi) {
    asm("mov.b64 {%0, %1}, %2;" : "=f"(lo), "=f"(hi) : "l"(v));
}
__device__ __forceinline__ ull fma2(ull a, ull b, ull c) {
    ull d; asm("fma.rn.f32x2 %0, %1, %2, %3;" : "=l"(d) : "l"(a), "l"(b), "l"(c)); return d;
}

struct Smem {
    ulonglong2 W01[H_][H_];   // 64KB  [k][u]: ((wi,wi),(wf,wf))
    ulonglong2 W23[H_][H_];   // 64KB  [k][u]: ((wg,wg),(wo,wo))
    float hsh[2][H_][HP];     // [buf][unit k][row], pitch 36
    float xsh[2][3][RT];      // x double buffer, transposed [i][row]
    float wdec[3][H_];
};
#define SMEM_BYTES ((int)sizeof(Smem))

extern __shared__ char smem_raw[];

__global__ void __launch_bounds__(NT, 1)
lstm_persistent_kernel(const float* __restrict__ x,      // [B, T, 3]
                       const float* __restrict__ Wih,    // [256, 3]
                       const float* __restrict__ Whh,    // [256, 64]
                       const float* __restrict__ bih,    // [256]
                       const float* __restrict__ bhh,    // [256]
                       const float* __restrict__ Wdec,   // [3, 64]
                       const float* __restrict__ bdec,   // [3]
                       float* __restrict__ out)          // [B, T, 3]
{
    Smem* S = (Smem*)smem_raw;
    const int tid  = threadIdx.x;
    const int row0 = blockIdx.x * RT;

    const int u  = tid >> 3;        // unit 0..63 owned by this thread
    const int rg = tid & 7;         // row group: rows 4rg .. 4rg+3

    // ---- setup -----------------------------------------------------------
    for (int idx = tid; idx < H_ * H_; idx += NT) {
        const int k = idx >> 6, uu = idx & 63;
        const float wi = Whh[(0 * H_ + uu) * H_ + k];
        const float wf = Whh[(1 * H_ + uu) * H_ + k];
        const float wg = Whh[(2 * H_ + uu) * H_ + k];
        const float wo = Whh[(3 * H_ + uu) * H_ + k];
        *(float4*)&S->W01[k][uu] = make_float4(wi, wi, wf, wf);
        *(float4*)&S->W23[k][uu] = make_float4(wg, wg, wo, wo);
    }
    for (int i = tid; i < 2 * H_ * HP; i += NT) ((float*)S->hsh)[i] = 0.0f;
    if (tid < 3 * H_) ((float*)S->wdec)[tid] = Wdec[tid];

    // per-thread W_ih (duplicated) and bias in registers
    ull wih2[4][3], biasp[4];
#pragma unroll
    for (int gt = 0; gt < 4; gt++) {
        const int g = gt * H_ + u;
        const float b = bih[g] + bhh[g];
        biasp[gt] = pack2(b, b);
#pragma unroll
        for (int i = 0; i < 3; i++) {
            const float wv = Wih[g * 3 + i];
            wih2[gt][i] = pack2(wv, wv);
        }
    }

    // decode / x-staging roles (threads 0..95)
    const int dro = tid >> 5;       // output/x component (0..2) for tid<96
    const int drr = tid & 31;       // row
    float bd = 0.0f;
    if (tid < 96) {
        bd = bdec[dro];
        S->xsh[0][dro][drr] = x[((size_t)(row0 + drr) * T_ + 0) * 3 + dro];
    }

    float c[4];
#pragma unroll
    for (int p = 0; p < 4; p++) c[p] = 0.0f;

    __syncthreads();

    // ---- timestep loop -----------------------------------------------------
    for (int t = 0; t < T_; t++) {
        const int A = t & 1, Bb = A ^ 1;

        // prefetch x(t+1): global latency hidden under the matvec
        float xp = 0.0f;
        if (tid < 96 && (t + 1) < T_)
            xp = x[((size_t)(row0 + drr) * T_ + (t + 1)) * 3 + dro];

        // decode previous step's h -> out[., t-1, .]
        if (t > 0 && tid < 96) {
            const float* hp_ = &S->hsh[A][0][drr];
            const float* wd  = &S->wdec[dro][0];
            float s0 = 0.f, s1 = 0.f, s2 = 0.f, s3 = 0.f;
#pragma unroll 4
            for (int k = 0; k < H_; k += 4) {
                s0 = fmaf(hp_[(k + 0) * HP], wd[k + 0], s0);
                s1 = fmaf(hp_[(k + 1) * HP], wd[k + 1], s1);
                s2 = fmaf(hp_[(k + 2) * HP], wd[k + 2], s2);
                s3 = fmaf(hp_[(k + 3) * HP], wd[k + 3], s3);
            }
            out[((size_t)(row0 + drr) * T_ + (t - 1)) * 3 + dro] = (s0 + s1) + (s2 + s3) + bd;
        }

        // accumulators: a[gate][pair]; pair 0 = rows (4rg,4rg+1), pair 1 = rows (4rg+2,4rg+3)
        ull a0[2], a1[2], a2[2], a3[2];
        a0[0] = biasp[0]; a0[1] = biasp[0];
        a1[0] = biasp[1]; a1[1] = biasp[1];
        a2[0] = biasp[2]; a2[1] = biasp[2];
        a3[0] = biasp[3]; a3[1] = biasp[3];

        // input contribution: + W_ih * x(t)
#pragma unroll
        for (int i = 0; i < 3; i++) {
            const ulonglong2 xv = *(const ulonglong2*)&S->xsh[A][i][4 * rg];
            a0[0] = fma2(xv.x, wih2[0][i], a0[0]);  a0[1] = fma2(xv.y, wih2[0][i], a0[1]);
            a1[0] = fma2(xv.x, wih2[1][i], a1[0]);  a1[1] = fma2(xv.y, wih2[1][i], a1[1]);
            a2[0] = fma2(xv.x, wih2[2][i], a2[0]);  a2[1] = fma2(xv.y, wih2[2][i], a2[1]);
            a3[0] = fma2(xv.x, wih2[3][i], a3[0]);  a3[1] = fma2(xv.y, wih2[3][i], a3[1]);
        }

        // recurrent matvec: per k, 3x LDS.128 + 8x fma.rn.f32x2
        {
            const float* hrow = &S->hsh[A][0][4 * rg];
            const ulonglong2* w01p = &S->W01[0][u];
            const ulonglong2* w23p = &S->W23[0][u];
#pragma unroll 4
            for (int k = 0; k < H_; k++) {
                const ulonglong2 hv  = *(const ulonglong2*)(hrow);   // 4 rows
                const ulonglong2 w01 = w01p[k * H_];
                const ulonglong2 w23 = w23p[k * H_];
                a0[0] = fma2(hv.x, w01.x, a0[0]);
                a0[1] = fma2(hv.y, w01.x, a0[1]);
                a1[0] = fma2(hv.x, w01.y, a1[0]);
                a1[1] = fma2(hv.y, w01.y, a1[1]);
                a2[0] = fma2(hv.x, w23.x, a2[0]);
                a2[1] = fma2(hv.y, w23.x, a2[1]);
                a3[0] = fma2(hv.x, w23.y, a3[0]);
                a3[1] = fma2(hv.y, w23.y, a3[1]);
                hrow += HP;
            }
        }

        // nonlinearities + state update on 4 (row, unit u) cells
        float hout[4];
#pragma unroll
        for (int pr = 0; pr < 2; pr++) {
            float gi0, gi1, gf0, gf1, gg0, gg1, go0, go1;
            unpack2(a0[pr], gi0, gi1);
            unpack2(a1[pr], gf0, gf1);
            unpack2(a2[pr], gg0, gg1);
            unpack2(a3[pr], go0, go1);
            {
                const float ig = sigf(gi0), fg = sigf(gf0), gg = tanhfast(gg0), og = sigf(go0);
                const float cn = fmaf(fg, c[2 * pr], ig * gg);
                c[2 * pr] = cn;
                hout[2 * pr] = og * tanhfast(cn);
            }
            {
                const float ig = sigf(gi1), fg = sigf(gf1), gg = tanhfast(gg1), og = sigf(go1);
                const float cn = fmaf(fg, c[2 * pr + 1], ig * gg);
                c[2 * pr + 1] = cn;
                hout[2 * pr + 1] = og * tanhfast(cn);
            }
        }
        *(float4*)&S->hsh[Bb][u][4 * rg] = make_float4(hout[0], hout[1], hout[2], hout[3]);

        // stage x(t+1)
        if (tid < 96) S->xsh[Bb][dro][drr] = xp;

        __syncthreads();
    }

    // epilogue: decode h(T-1) (buffer 0 after the last flip)
    if (tid < 96) {
        const float* hp_ = &S->hsh[0][0][drr];
        const float* wd  = &S->wdec[dro][0];
        float s0 = 0.f, s1 = 0.f, s2 = 0.f, s3 = 0.f;
#pragma unroll 4
        for (int k = 0; k < H_; k += 4) {
            s0 = fmaf(hp_[(k + 0) * HP], wd[k + 0], s0);
            s1 = fmaf(hp_[(k + 1) * HP], wd[k + 1], s1);
            s2 = fmaf(hp_[(k + 2) * HP], wd[k + 2], s2);
            s3 = fmaf(hp_[(k + 3) * HP], wd[k + 3], s3);
        }
        out[((size_t)(row0 + drr) * T_ + (T_ - 1)) * 3 + dro] = (s0 + s1) + (s2 + s3) + bd;
    }
}

extern "C" void kernel_launch(void* const* d_in, const int* in_sizes, int n_in,
                              void* d_out, int out_size) {
    const float* x    = (const float*)d_in[0];
    const float* Wih  = (const float*)d_in[1];
    const float* Whh  = (const float*)d_in[2];
    const float* bih  = (const float*)d_in[3];
    const float* bhh  = (const float*)d_in[4];
    const float* Wdec = (const float*)d_in[5];
    const float* bdec = (const float*)d_in[6];
    float* out = (float*)d_out;

    cudaFuncSetAttribute(lstm_persistent_kernel,
                         cudaFuncAttributeMaxDynamicSharedMemorySize, SMEM_BYTES);
    lstm_persistent_kernel<<<B_ / RT, NT, SMEM_BYTES>>>(x, Wih, Whh, bih, bhh, Wdec, bdec, out);
}

// round 9
// speedup vs baseline: 1.1476x; 1.1462x over previous
#include <cuda_runtime.h>

// LSTMAnomalyDetector: B=4096, T=512, I=3, H=64 (PyTorch gate order i,f,g,o)
//
// Round-9 = round-8 design with the wdec-init bug fixed (192 floats vs NT=128
// threads -> strided loop). grid=256 CTAs x 128 threads, RT=16 rows/CTA ->
// 2 CTAs per SM with INDEPENDENT barrier domains (tail of one CTA overlaps
// matvec of the other). Thread owns (unit u) x (8 rows).
// Gate-packed accumulators: acc_if=(i,f), acc_go=(g,o); weights natural float4
// (wi,wf,wg,wo) -> 64KB table; h stored DUPLICATED (h,h).
// Per k per thread: 5 LDS.128 + 16 fma.rn.f32x2.

#define B_   4096
#define T_   512
#define H_   64
#define RT   16      // rows per CTA
#define NT   128     // threads per CTA
#define HPD  18      // hdup row pitch in ulls (16 used + pad, keeps 16B align)

typedef unsigned long long ull;

__device__ __forceinline__ float tanhfast(float x) {
    float y; asm("tanh.approx.f32 %0, %1;" : "=f"(y) : "f"(x)); return y;
}
__device__ __forceinline__ float sigf(float x) {
    return fmaf(0.5f, tanhfast(0.5f * x), 0.5f);
}
__device__ __forceinline__ ull pack2(float a, float b) {   // a -> low lane
    ull r; asm("mov.b64 %0, {%1, %2};" : "=l"(r) : "f"(a), "f"(b)); return r;
}
__device__ __forceinline__ void unpack2(ull v, float& lo, float& hi) {
    asm("mov.b64 {%0, %1}, %2;" : "=f"(lo), "=f"(hi) : "l"(v));
}
__device__ __forceinline__ ull fma2(ull a, ull b, ull c) {
    ull d; asm("fma.rn.f32x2 %0, %1, %2, %3;" : "=l"(d) : "l"(a), "l"(b), "l"(c)); return d;
}

struct Smem {
    ulonglong2 W4[H_][H_];     // 64KB [k][u]: .x=(wi,wf) .y=(wg,wo)
    ull hdup[2][H_][HPD];      // 18KB [buf][k][row]: (h,h) duplicated, pitch 18
    ull xdup[2][3][RT];        // [buf][comp][row]: (x,x) duplicated
    float wdec[3][H_];
};
#define SMEM_BYTES ((int)sizeof(Smem))

extern __shared__ char smem_raw[];

__global__ void __launch_bounds__(NT, 2)
lstm_persistent_kernel(const float* __restrict__ x,      // [B, T, 3]
                       const float* __restrict__ Wih,    // [256, 3]
                       const float* __restrict__ Whh,    // [256, 64]
                       const float* __restrict__ bih,    // [256]
                       const float* __restrict__ bhh,    // [256]
                       const float* __restrict__ Wdec,   // [3, 64]
                       const float* __restrict__ bdec,   // [3]
                       float* __restrict__ out)          // [B, T, 3]
{
    Smem* S = (Smem*)smem_raw;
    const int tid  = threadIdx.x;
    const int row0 = blockIdx.x * RT;

    const int u  = tid >> 1;        // unit 0..63
    const int rg = tid & 1;         // rows 8rg .. 8rg+7

    // ---- setup -----------------------------------------------------------
    // W4[k][u] = (wi, wf, wg, wo) for unit u at input index k (natural, no dup)
    for (int idx = tid; idx < H_ * H_; idx += NT) {
        const int k = idx >> 6, uu = idx & 63;
        const float wi = Whh[(0 * H_ + uu) * H_ + k];
        const float wf = Whh[(1 * H_ + uu) * H_ + k];
        const float wg = Whh[(2 * H_ + uu) * H_ + k];
        const float wo = Whh[(3 * H_ + uu) * H_ + k];
        *(float4*)&S->W4[k][uu] = make_float4(wi, wf, wg, wo);
    }
    for (int i = tid; i < 2 * H_ * HPD; i += NT) ((ull*)S->hdup)[i] = 0ull;
    // FIX (round-8 bug): 3*H_ = 192 > NT = 128 -> must be a strided loop.
    for (int i = tid; i < 3 * H_; i += NT) ((float*)S->wdec)[i] = Wdec[i];

    // per-thread bias / W_ih, gate-packed: low lane = first gate of the pair
    const ull bias_if = pack2(bih[u]        + bhh[u],
                              bih[H_ + u]   + bhh[H_ + u]);
    const ull bias_go = pack2(bih[2*H_ + u] + bhh[2*H_ + u],
                              bih[3*H_ + u] + bhh[3*H_ + u]);
    ull wih_if[3], wih_go[3];
#pragma unroll
    for (int i = 0; i < 3; i++) {
        wih_if[i] = pack2(Wih[u * 3 + i],          Wih[(H_ + u) * 3 + i]);
        wih_go[i] = pack2(Wih[(2*H_ + u) * 3 + i], Wih[(3*H_ + u) * 3 + i]);
    }

    // decode / x-staging roles: threads 0..47 -> (comp o, row r)
    const int o_ = tid >> 4;        // 0..2 (for tid<48)
    const int r_ = tid & 15;        // 0..15
    float bd = 0.0f;
    if (tid < 48) {
        bd = bdec[o_];
        const float xv = x[((size_t)(row0 + r_) * T_ + 0) * 3 + o_];
        S->xdup[0][o_][r_] = pack2(xv, xv);
    }

    float c[8];
#pragma unroll
    for (int p = 0; p < 8; p++) c[p] = 0.0f;

    __syncthreads();

    // ---- timestep loop -----------------------------------------------------
    for (int t = 0; t < T_; t++) {
        const int A = t & 1, Bb = A ^ 1;

        // prefetch x(t+1): long global latency hidden under decode+matvec
        float xp = 0.0f;
        if (tid < 48 && (t + 1) < T_)
            xp = x[((size_t)(row0 + r_) * T_ + (t + 1)) * 3 + o_];

        // decode previous step's h -> out[., t-1, .]
        if (t > 0 && tid < 48) {
            const float* hp_ = (const float*)&S->hdup[A][0][r_];  // low lane of (h,h)
            const float* wd  = &S->wdec[o_][0];
            float s0 = 0.f, s1 = 0.f, s2 = 0.f, s3 = 0.f;
#pragma unroll 4
            for (int k = 0; k < H_; k += 4) {
                s0 = fmaf(hp_[(k + 0) * (2 * HPD)], wd[k + 0], s0);
                s1 = fmaf(hp_[(k + 1) * (2 * HPD)], wd[k + 1], s1);
                s2 = fmaf(hp_[(k + 2) * (2 * HPD)], wd[k + 2], s2);
                s3 = fmaf(hp_[(k + 3) * (2 * HPD)], wd[k + 3], s3);
            }
            out[((size_t)(row0 + r_) * T_ + (t - 1)) * 3 + o_] = (s0 + s1) + (s2 + s3) + bd;
        }

        // accumulators: acc_if[j]=(i,f), acc_go[j]=(g,o) for row 8rg+j
        ull acc_if[8], acc_go[8];
#pragma unroll
        for (int j = 0; j < 8; j++) { acc_if[j] = bias_if; acc_go[j] = bias_go; }

        // input contribution: x duplicated in smem, weights packed per gate-pair
#pragma unroll
        for (int i = 0; i < 3; i++) {
            const ulonglong2* xp2 = (const ulonglong2*)&S->xdup[A][i][8 * rg];
#pragma unroll
            for (int q = 0; q < 4; q++) {
                const ulonglong2 xv = xp2[q];
                acc_if[2*q]   = fma2(xv.x, wih_if[i], acc_if[2*q]);
                acc_go[2*q]   = fma2(xv.x, wih_go[i], acc_go[2*q]);
                acc_if[2*q+1] = fma2(xv.y, wih_if[i], acc_if[2*q+1]);
                acc_go[2*q+1] = fma2(xv.y, wih_go[i], acc_go[2*q+1]);
            }
        }

        // recurrent matvec: per k, 5x LDS.128 + 16x fma.rn.f32x2
        {
            const ulonglong2* wp = &S->W4[0][u];          // stride H_ per k
            const ull* hp = &S->hdup[A][0][8 * rg];       // stride HPD per k
#pragma unroll 4
            for (int k = 0; k < H_; k++) {
                const ulonglong2 wv = wp[k * H_];
                const ulonglong2 h01 = *(const ulonglong2*)(hp + k * HPD + 0);
                const ulonglong2 h23 = *(const ulonglong2*)(hp + k * HPD + 2);
                const ulonglong2 h45 = *(const ulonglong2*)(hp + k * HPD + 4);
                const ulonglong2 h67 = *(const ulonglong2*)(hp + k * HPD + 6);
                acc_if[0] = fma2(h01.x, wv.x, acc_if[0]);
                acc_go[0] = fma2(h01.x, wv.y, acc_go[0]);
                acc_if[1] = fma2(h01.y, wv.x, acc_if[1]);
                acc_go[1] = fma2(h01.y, wv.y, acc_go[1]);
                acc_if[2] = fma2(h23.x, wv.x, acc_if[2]);
                acc_go[2] = fma2(h23.x, wv.y, acc_go[2]);
                acc_if[3] = fma2(h23.y, wv.x, acc_if[3]);
                acc_go[3] = fma2(h23.y, wv.y, acc_go[3]);
                acc_if[4] = fma2(h45.x, wv.x, acc_if[4]);
                acc_go[4] = fma2(h45.x, wv.y, acc_go[4]);
                acc_if[5] = fma2(h45.y, wv.x, acc_if[5]);
                acc_go[5] = fma2(h45.y, wv.y, acc_go[5]);
                acc_if[6] = fma2(h67.x, wv.x, acc_if[6]);
                acc_go[6] = fma2(h67.x, wv.y, acc_go[6]);
                acc_if[7] = fma2(h67.y, wv.x, acc_if[7]);
                acc_go[7] = fma2(h67.y, wv.y, acc_go[7]);
            }
        }

        // nonlinearities + state update on 8 (row, unit u) cells
        float hout[8];
#pragma unroll
        for (int j = 0; j < 8; j++) {
            float gi, gf, gg, go;
            unpack2(acc_if[j], gi, gf);
            unpack2(acc_go[j], gg, go);
            const float ig = sigf(gi), fg = sigf(gf);
            const float gt = tanhfast(gg), og = sigf(go);
            const float cn = fmaf(fg, c[j], ig * gt);
            c[j] = cn;
            hout[j] = og * tanhfast(cn);
        }
        {
            ull* hd = &S->hdup[Bb][u][8 * rg];
#pragma unroll
            for (int q = 0; q < 4; q++) {
                ulonglong2 v;
                v.x = pack2(hout[2*q],     hout[2*q]);
                v.y = pack2(hout[2*q + 1], hout[2*q + 1]);
                *(ulonglong2*)(hd + 2*q) = v;
            }
        }

        // stage x(t+1), duplicated
        if (tid < 48) S->xdup[Bb][o_][r_] = pack2(xp, xp);

        __syncthreads();
    }

    // epilogue: decode h(T-1) (last store went to buffer 0)
    if (tid < 48) {
        const float* hp_ = (const float*)&S->hdup[0][0][r_];
        const float* wd  = &S->wdec[o_][0];
        float s0 = 0.f, s1 = 0.f, s2 = 0.f, s3 = 0.f;
#pragma unroll 4
        for (int k = 0; k < H_; k += 4) {
            s0 = fmaf(hp_[(k + 0) * (2 * HPD)], wd[k + 0], s0);
            s1 = fmaf(hp_[(k + 1) * (2 * HPD)], wd[k + 1], s1);
            s2 = fmaf(hp_[(k + 2) * (2 * HPD)], wd[k + 2], s2);
            s3 = fmaf(hp_[(k + 3) * (2 * HPD)], wd[k + 3], s3);
        }
        out[((size_t)(row0 + r_) * T_ + (T_ - 1)) * 3 + o_] = (s0 + s1) + (s2 + s3) + bd;
    }
}

extern "C" void kernel_launch(void* const* d_in, const int* in_sizes, int n_in,
                              void* d_out, int out_size) {
    const float* x    = (const float*)d_in[0];
    const float* Wih  = (const float*)d_in[1];
    const float* Whh  = (const float*)d_in[2];
    const float* bih  = (const float*)d_in[3];
    const float* bhh  = (const float*)d_in[4];
    const float* Wdec = (const float*)d_in[5];
    const float* bdec = (const float*)d_in[6];
    float* out = (float*)d_out;

    cudaFuncSetAttribute(lstm_persistent_kernel,
                         cudaFuncAttributeMaxDynamicSharedMemorySize, SMEM_BYTES);
    lstm_persistent_kernel<<<B_ / RT, NT, SMEM_BYTES>>>(x, Wih, Whh, bih, bhh, Wdec, bdec, out);
}